// round 1
// baseline (speedup 1.0000x reference)
#include <cuda_runtime.h>
#include <cstdint>
#include <math_constants.h>

#define NV   4096
#define DV   256
#define TK   20
#define TKI  10
#define NSEL 30
#define MLAB 5
#define NW   (NV/32)   // 128 bitset words per row

// -------- scratch (static device globals; no allocation) --------
__device__ float    g_sim[(size_t)NV * NV];   // 64 MB
__device__ int      g_knn[NV * NSEL];
__device__ unsigned g_bits[NV * NW];

// ============================================================================
// Phase 1: sim = E * E^T  (fp32, symmetric: compute upper-tri blocks, mirror)
// 64x64 tile, 256 threads, 4x4 per thread, BK=16
// ============================================================================
__global__ void __launch_bounds__(256) gemm_sym_kernel(const float* __restrict__ E) {
    int bx = blockIdx.x;   // col block
    int by = blockIdx.y;   // row block
    if (bx < by) return;   // upper triangle only

    __shared__ __align__(16) float As[16][68];
    __shared__ __align__(16) float Bs[16][68];

    int tid = threadIdx.x;
    int tx = tid & 15;
    int ty = tid >> 4;
    int lr = tid >> 2;          // 0..63 load row
    int lc = (tid & 3) * 4;     // 0,4,8,12 load col (k offset)

    int rowBase = by * 64;
    int colBase = bx * 64;

    float acc[4][4];
#pragma unroll
    for (int q = 0; q < 4; q++)
#pragma unroll
        for (int p = 0; p < 4; p++) acc[q][p] = 0.0f;

    const float4* E4 = (const float4*)E;

#pragma unroll 1
    for (int k0 = 0; k0 < DV; k0 += 16) {
        float4 a = E4[((size_t)(rowBase + lr) * DV + k0 + lc) >> 2];
        float4 b = E4[((size_t)(colBase + lr) * DV + k0 + lc) >> 2];
        As[lc + 0][lr] = a.x; As[lc + 1][lr] = a.y; As[lc + 2][lr] = a.z; As[lc + 3][lr] = a.w;
        Bs[lc + 0][lr] = b.x; Bs[lc + 1][lr] = b.y; Bs[lc + 2][lr] = b.z; Bs[lc + 3][lr] = b.w;
        __syncthreads();
#pragma unroll
        for (int kk = 0; kk < 16; kk++) {
            float4 av = *(const float4*)&As[kk][ty * 4];
            float4 bv = *(const float4*)&Bs[kk][tx * 4];
            float ar[4] = {av.x, av.y, av.z, av.w};
            float br[4] = {bv.x, bv.y, bv.z, bv.w};
#pragma unroll
            for (int q = 0; q < 4; q++)
#pragma unroll
                for (int p = 0; p < 4; p++) acc[q][p] = fmaf(ar[q], br[p], acc[q][p]);
        }
        __syncthreads();
    }

    // normal write: rows rowBase+ty*4+q, cols colBase+tx*4..+3 (coalesced float4)
#pragma unroll
    for (int q = 0; q < 4; q++) {
        float4 v = make_float4(acc[q][0], acc[q][1], acc[q][2], acc[q][3]);
        *(float4*)&g_sim[(size_t)(rowBase + ty * 4 + q) * NV + colBase + tx * 4] = v;
    }
    // mirror write (transposed); skip diag block (identical values)
    if (bx != by) {
#pragma unroll
        for (int p = 0; p < 4; p++) {
            float4 v = make_float4(acc[0][p], acc[1][p], acc[2][p], acc[3][p]);
            *(float4*)&g_sim[(size_t)(colBase + tx * 4 + p) * NV + rowBase + ty * 4] = v;
        }
    }
}

// ============================================================================
// Phase 2: per-row top-k selection (exact jax.lax.top_k semantics:
// descending value, ties -> lower index), kNN list + membership bitset.
// One block (256 threads) per row.
// ============================================================================
__global__ void __launch_bounds__(256) topk_kernel(const int* __restrict__ bid) {
    int i = blockIdx.x;
    int tid = threadIdx.x;

    __shared__ float sv[NV];                 // 16 KB sim row
    __shared__ int   sb[NV];                 // 16 KB batch ids
    __shared__ unsigned long long warpRes[8];
    __shared__ int   chosen[TK + 1 + TKI];   // 31
    __shared__ unsigned bitsS[NW];

    const float4* row4 = (const float4*)&g_sim[(size_t)i * NV];
    for (int j = tid; j < NV / 4; j += 256) ((float4*)sv)[j] = row4[j];
    for (int j = tid; j < NV; j += 256) sb[j] = bid[j];
    for (int j = tid; j < NW; j += 256) bitsS[j] = 0;
    __syncthreads();

    int myb = sb[i];

    // phase 0: intra (same group), top 21; phase 1: inter (diff group), top 10
    for (int phase = 0; phase < 2; phase++) {
        int cnt = (phase == 0) ? (TK + 1) : TKI;
        int base = (phase == 0) ? 0 : (TK + 1);
        bool wantSame = (phase == 0);
        for (int t = 0; t < cnt; t++) {
            unsigned long long best = 0ull;
            for (int j = tid; j < NV; j += 256) {
                if ((sb[j] == myb) == wantSame) {
                    unsigned vb = __float_as_uint(sv[j]);
                    vb = (vb & 0x80000000u) ? ~vb : (vb | 0x80000000u);
                    unsigned long long key =
                        ((unsigned long long)vb << 32) | (unsigned)(NV - j);
                    if (key > best) best = key;
                }
            }
#pragma unroll
            for (int o = 16; o > 0; o >>= 1) {
                unsigned long long other = __shfl_down_sync(0xffffffffu, best, o);
                if (other > best) best = other;
            }
            if ((tid & 31) == 0) warpRes[tid >> 5] = best;
            __syncthreads();
            if (tid < 32) {
                unsigned long long b = (tid < 8) ? warpRes[tid] : 0ull;
#pragma unroll
                for (int o = 4; o > 0; o >>= 1) {
                    unsigned long long other = __shfl_down_sync(0xffffffffu, b, o);
                    if (other > b) b = other;
                }
                if (tid == 0) {
                    int w = NV - (int)(b & 0xffffffffull);
                    chosen[base + t] = w;
                    sv[w] = -CUDART_INF_F;   // remove from candidates
                }
            }
            __syncthreads();
        }
    }

    // final knn row: intra ranks 1..20, then inter ranks 0..9
    if (tid < NSEL) {
        int j = (tid < TK) ? chosen[1 + tid] : chosen[(TK + 1) + (tid - TK)];
        g_knn[i * NSEL + tid] = j;
        atomicOr(&bitsS[j >> 5], 1u << (j & 31));
    }
    __syncthreads();
    for (int w = tid; w < NW; w += 256) g_bits[i * NW + w] = bitsS[w];
}

// ============================================================================
// Phase 3: mutual check -> scatter locality + all_close
// ============================================================================
__global__ void __launch_bounds__(256) finalize_kernel(
    const float* __restrict__ adj, const int* __restrict__ cl,
    float* __restrict__ out) {
    int id = blockIdx.x * blockDim.x + threadIdx.x;
    if (id >= NV * NSEL) return;
    int i = id / NSEL;
    int j = g_knn[id];

    bool mut = (j != i) && ((g_bits[j * NW + (i >> 5)] >> (i & 31)) & 1u);
    if (mut) out[(size_t)i * NV + j] = adj[(size_t)i * NV + j];

    bool ac = mut;
    if (!ac) {
        ac = true;
#pragma unroll
        for (int m = 0; m < MLAB; m++)
            if (cl[m * NV + i] != cl[m * NV + j]) ac = false;
    }
    out[(size_t)NV * NV + id] = ac ? 1.0f : 0.0f;
}

// ============================================================================
extern "C" void kernel_launch(void* const* d_in, const int* in_sizes, int n_in,
                              void* d_out, int out_size) {
    const float* adj = (const float*)d_in[0];
    const float* E   = (const float*)d_in[1];
    const int*   bid = (const int*)d_in[2];
    const int*   cl  = (const int*)d_in[3];
    float* out = (float*)d_out;

    dim3 grid(NV / 64, NV / 64);
    gemm_sym_kernel<<<grid, 256>>>(E);
    topk_kernel<<<NV, 256>>>(bid);
    cudaMemsetAsync(out, 0, (size_t)NV * NV * sizeof(float));
    finalize_kernel<<<(NV * NSEL + 255) / 256, 256>>>(adj, cl, out);
}

// round 2
// speedup vs baseline: 2.2896x; 2.2896x over previous
#include <cuda_runtime.h>
#include <cstdint>
#include <math_constants.h>

#define NV   4096
#define DV   256
#define TK   20
#define TKI  10
#define NSEL 30
#define MLAB 5
#define NW   (NV/32)       // 128 bitset words per row
#define NCHUNK 64          // tournament chunks (64 elems each)

typedef unsigned long long ull;
#define MSB (1ull << 63)

// -------- scratch (static device globals; no allocation) --------
__device__ float    g_sim[(size_t)NV * NV];   // 64 MB
__device__ int      g_knn[NV * NSEL];
__device__ unsigned g_bits[NV * NW];

// ============================================================================
// Phase 1: sim = E * E^T  (fp32, symmetric: compute upper-tri blocks, mirror)
// ============================================================================
__global__ void __launch_bounds__(256) gemm_sym_kernel(const float* __restrict__ E) {
    int bx = blockIdx.x;
    int by = blockIdx.y;
    if (bx < by) return;

    __shared__ __align__(16) float As[16][68];
    __shared__ __align__(16) float Bs[16][68];

    int tid = threadIdx.x;
    int tx = tid & 15;
    int ty = tid >> 4;
    int lr = tid >> 2;
    int lc = (tid & 3) * 4;

    int rowBase = by * 64;
    int colBase = bx * 64;

    float acc[4][4];
#pragma unroll
    for (int q = 0; q < 4; q++)
#pragma unroll
        for (int p = 0; p < 4; p++) acc[q][p] = 0.0f;

    const float4* E4 = (const float4*)E;

#pragma unroll 1
    for (int k0 = 0; k0 < DV; k0 += 16) {
        float4 a = E4[((size_t)(rowBase + lr) * DV + k0 + lc) >> 2];
        float4 b = E4[((size_t)(colBase + lr) * DV + k0 + lc) >> 2];
        As[lc + 0][lr] = a.x; As[lc + 1][lr] = a.y; As[lc + 2][lr] = a.z; As[lc + 3][lr] = a.w;
        Bs[lc + 0][lr] = b.x; Bs[lc + 1][lr] = b.y; Bs[lc + 2][lr] = b.z; Bs[lc + 3][lr] = b.w;
        __syncthreads();
#pragma unroll
        for (int kk = 0; kk < 16; kk++) {
            float4 av = *(const float4*)&As[kk][ty * 4];
            float4 bv = *(const float4*)&Bs[kk][tx * 4];
            float ar[4] = {av.x, av.y, av.z, av.w};
            float br[4] = {bv.x, bv.y, bv.z, bv.w};
#pragma unroll
            for (int q = 0; q < 4; q++)
#pragma unroll
                for (int p = 0; p < 4; p++) acc[q][p] = fmaf(ar[q], br[p], acc[q][p]);
        }
        __syncthreads();
    }

#pragma unroll
    for (int q = 0; q < 4; q++) {
        float4 v = make_float4(acc[q][0], acc[q][1], acc[q][2], acc[q][3]);
        *(float4*)&g_sim[(size_t)(rowBase + ty * 4 + q) * NV + colBase + tx * 4] = v;
    }
    if (bx != by) {
#pragma unroll
        for (int p = 0; p < 4; p++) {
            float4 v = make_float4(acc[0][p], acc[1][p], acc[2][p], acc[3][p]);
            *(float4*)&g_sim[(size_t)(colBase + tx * 4 + p) * NV + rowBase + ty * 4] = v;
        }
    }
}

// ============================================================================
// Phase 2: tournament top-k.
// key = same_flag<<63 | ordered(v)<<13 | (NV - j)
//   intra max  = plain max over keys
//   inter max  = max over keys ^ MSB
//   removed    = key set to MSB (neutral in both phases)
// ============================================================================
__device__ __forceinline__ unsigned f2ord(float f) {
    unsigned b = __float_as_uint(f);
    return (b & 0x80000000u) ? ~b : (b | 0x80000000u);
}
__device__ __forceinline__ ull warp_max_bfly(ull m) {
#pragma unroll
    for (int o = 16; o > 0; o >>= 1) {
        ull other = __shfl_xor_sync(0xffffffffu, m, o);
        if (other > m) m = other;
    }
    return m;
}

__global__ void __launch_bounds__(256) topk_kernel(const int* __restrict__ bid) {
    int i = blockIdx.x;
    int tid = threadIdx.x;
    int lane = tid & 31;
    int wid = tid >> 5;

    __shared__ ull keys[NV];          // 32 KB
    __shared__ ull cmax[NCHUNK];
    __shared__ int chosen[TK + 1 + TKI];
    __shared__ unsigned bitsS[NW];

    int myb = __ldg(&bid[i]);

    // ---- build keys (one pass, vectorized) ----
    const float4* row4 = (const float4*)&g_sim[(size_t)i * NV];
    const int4*   bid4 = (const int4*)bid;
    for (int t = tid; t < NV / 4; t += 256) {
        float4 v = row4[t];
        int4   g = __ldg(&bid4[t]);
        int j0 = t * 4;
        keys[j0 + 0] = ((g.x == myb) ? MSB : 0) | ((ull)f2ord(v.x) << 13) | (unsigned)(NV - (j0 + 0));
        keys[j0 + 1] = ((g.y == myb) ? MSB : 0) | ((ull)f2ord(v.y) << 13) | (unsigned)(NV - (j0 + 1));
        keys[j0 + 2] = ((g.z == myb) ? MSB : 0) | ((ull)f2ord(v.z) << 13) | (unsigned)(NV - (j0 + 2));
        keys[j0 + 3] = ((g.w == myb) ? MSB : 0) | ((ull)f2ord(v.w) << 13) | (unsigned)(NV - (j0 + 3));
    }
    for (int w = tid; w < NW; w += 256) bitsS[w] = 0;
    __syncthreads();

    // ---- two phases: intra (xm=0, 21 picks), inter (xm=MSB, 10 picks) ----
#pragma unroll 1
    for (int phase = 0; phase < 2; phase++) {
        ull xm = phase ? MSB : 0ull;
        int cnt  = phase ? TKI : (TK + 1);
        int base = phase ? (TK + 1) : 0;

        // build chunk maxima: warp w -> chunks 8w..8w+7
#pragma unroll
        for (int cc = 0; cc < 8; cc++) {
            int c = wid * 8 + cc;
            ull a = keys[c * 64 + lane] ^ xm;
            ull b = keys[c * 64 + 32 + lane] ^ xm;
            ull m = a > b ? a : b;
            m = warp_max_bfly(m);
            if (lane == 0) cmax[c] = m;
        }
        __syncthreads();

        // warp 0 extracts sequentially
        if (wid == 0) {
#pragma unroll 1
            for (int t = 0; t < cnt; t++) {
                ull a = cmax[lane];
                ull b = cmax[lane + 32];
                ull m = a > b ? a : b;
                m = warp_max_bfly(m);
                int j = NV - (int)(m & 0x1FFFull);
                int c = j >> 6;
                if (lane == 0) {
                    chosen[base + t] = j;
                    keys[j] = MSB;           // remove
                }
                __syncwarp();
                ull ra = keys[c * 64 + lane] ^ xm;
                ull rb = keys[c * 64 + 32 + lane] ^ xm;
                ull rm = ra > rb ? ra : rb;
                rm = warp_max_bfly(rm);
                if (lane == 0) cmax[c] = rm;
                __syncwarp();
            }
        }
        __syncthreads();
    }

    // ---- emit knn row + membership bitset ----
    if (tid < NSEL) {
        int j = (tid < TK) ? chosen[1 + tid] : chosen[(TK + 1) + (tid - TK)];
        g_knn[i * NSEL + tid] = j;
        atomicOr(&bitsS[j >> 5], 1u << (j & 31));
    }
    __syncthreads();
    for (int w = tid; w < NW; w += 256) g_bits[i * NW + w] = bitsS[w];
}

// ============================================================================
// Phase 3: mutual check -> scatter locality + all_close
// ============================================================================
__global__ void __launch_bounds__(256) finalize_kernel(
    const float* __restrict__ adj, const int* __restrict__ cl,
    float* __restrict__ out) {
    int id = blockIdx.x * blockDim.x + threadIdx.x;
    if (id >= NV * NSEL) return;
    int i = id / NSEL;
    int j = g_knn[id];

    bool mut = (j != i) && ((g_bits[j * NW + (i >> 5)] >> (i & 31)) & 1u);
    if (mut) out[(size_t)i * NV + j] = adj[(size_t)i * NV + j];

    bool ac = mut;
    if (!ac) {
        ac = true;
#pragma unroll
        for (int m = 0; m < MLAB; m++)
            if (cl[m * NV + i] != cl[m * NV + j]) ac = false;
    }
    out[(size_t)NV * NV + id] = ac ? 1.0f : 0.0f;
}

// ============================================================================
extern "C" void kernel_launch(void* const* d_in, const int* in_sizes, int n_in,
                              void* d_out, int out_size) {
    const float* adj = (const float*)d_in[0];
    const float* E   = (const float*)d_in[1];
    const int*   bid = (const int*)d_in[2];
    const int*   cl  = (const int*)d_in[3];
    float* out = (float*)d_out;

    dim3 grid(NV / 64, NV / 64);
    gemm_sym_kernel<<<grid, 256>>>(E);
    topk_kernel<<<NV, 256>>>(bid);
    cudaMemsetAsync(out, 0, (size_t)NV * NV * sizeof(float));
    finalize_kernel<<<(NV * NSEL + 255) / 256, 256>>>(adj, cl, out);
}

// round 3
// speedup vs baseline: 2.3437x; 1.0236x over previous
#include <cuda_runtime.h>
#include <cstdint>
#include <math_constants.h>

#define NV   4096
#define DV   256
#define TK   20
#define TKI  10
#define NSEL 30
#define MLAB 5
#define NW   (NV/32)       // 128 bitset words per row
#define NCHUNK 64          // tournament chunks (64 elems each)

typedef unsigned long long ull;
#define MSB (1ull << 63)

// -------- scratch (static device globals; no allocation) --------
__device__ float    g_sim[(size_t)NV * NV];   // 64 MB
__device__ int      g_knn[NV * NSEL];
__device__ unsigned g_bits[NV * NW];

// ============================================================================
// Phase 1: sim = E * E^T  (fp32, symmetric: upper-tri blocks + mirror)
// 128x128 tile, 256 threads, 8x8 per thread, BK=8, double-buffered smem
// ============================================================================
__global__ void __launch_bounds__(256, 2) gemm_sym_kernel(const float* __restrict__ E) {
    int bx = blockIdx.x;
    int by = blockIdx.y;
    if (bx < by) return;

    __shared__ __align__(16) float As[2][8][132];
    __shared__ __align__(16) float Bs[2][8][132];

    int tid = threadIdx.x;
    int tx = tid & 15;          // 0..15 -> col group *8
    int ty = tid >> 4;          // 0..15 -> row group *8
    int lr = tid >> 1;          // 0..127 load row
    int lc = (tid & 1) * 4;     // 0 or 4  load k-offset

    int rowBase = by * 128;
    int colBase = bx * 128;

    float acc[8][8];
#pragma unroll
    for (int q = 0; q < 8; q++)
#pragma unroll
        for (int p = 0; p < 8; p++) acc[q][p] = 0.0f;

    const float4* E4 = (const float4*)E;

    // preload k-tile 0
    float4 a = E4[((unsigned)(rowBase + lr) * DV + lc) >> 2];
    float4 b = E4[((unsigned)(colBase + lr) * DV + lc) >> 2];
    As[0][lc + 0][lr] = a.x; As[0][lc + 1][lr] = a.y; As[0][lc + 2][lr] = a.z; As[0][lc + 3][lr] = a.w;
    Bs[0][lc + 0][lr] = b.x; Bs[0][lc + 1][lr] = b.y; Bs[0][lc + 2][lr] = b.z; Bs[0][lc + 3][lr] = b.w;
    __syncthreads();

#pragma unroll 1
    for (int kt = 0; kt < DV / 8; kt++) {
        int cur = kt & 1;
        int nxt = cur ^ 1;
        if (kt + 1 < DV / 8) {
            int k0 = (kt + 1) * 8;
            a = E4[((unsigned)(rowBase + lr) * DV + k0 + lc) >> 2];
            b = E4[((unsigned)(colBase + lr) * DV + k0 + lc) >> 2];
        }
#pragma unroll
        for (int kk = 0; kk < 8; kk++) {
            float4 av0 = *(const float4*)&As[cur][kk][ty * 8];
            float4 av1 = *(const float4*)&As[cur][kk][ty * 8 + 4];
            float4 bv0 = *(const float4*)&Bs[cur][kk][tx * 8];
            float4 bv1 = *(const float4*)&Bs[cur][kk][tx * 8 + 4];
            float ar[8] = {av0.x, av0.y, av0.z, av0.w, av1.x, av1.y, av1.z, av1.w};
            float br[8] = {bv0.x, bv0.y, bv0.z, bv0.w, bv1.x, bv1.y, bv1.z, bv1.w};
#pragma unroll
            for (int q = 0; q < 8; q++)
#pragma unroll
                for (int p = 0; p < 8; p++) acc[q][p] = fmaf(ar[q], br[p], acc[q][p]);
        }
        if (kt + 1 < DV / 8) {
            As[nxt][lc + 0][lr] = a.x; As[nxt][lc + 1][lr] = a.y;
            As[nxt][lc + 2][lr] = a.z; As[nxt][lc + 3][lr] = a.w;
            Bs[nxt][lc + 0][lr] = b.x; Bs[nxt][lc + 1][lr] = b.y;
            Bs[nxt][lc + 2][lr] = b.z; Bs[nxt][lc + 3][lr] = b.w;
            __syncthreads();
        }
    }

    // normal write (coalesced float4 pairs per row)
#pragma unroll
    for (int q = 0; q < 8; q++) {
        size_t base = (size_t)(rowBase + ty * 8 + q) * NV + colBase + tx * 8;
        *(float4*)&g_sim[base]     = make_float4(acc[q][0], acc[q][1], acc[q][2], acc[q][3]);
        *(float4*)&g_sim[base + 4] = make_float4(acc[q][4], acc[q][5], acc[q][6], acc[q][7]);
    }
    // mirror write (transposed); skip diag block
    if (bx != by) {
#pragma unroll
        for (int p = 0; p < 8; p++) {
            size_t base = (size_t)(colBase + tx * 8 + p) * NV + rowBase + ty * 8;
            *(float4*)&g_sim[base]     = make_float4(acc[0][p], acc[1][p], acc[2][p], acc[3][p]);
            *(float4*)&g_sim[base + 4] = make_float4(acc[4][p], acc[5][p], acc[6][p], acc[7][p]);
        }
    }
}

// ============================================================================
// Phase 2: tournament top-k.
// key = same_flag<<63 | ordered(v)<<13 | (NV - j)
// ============================================================================
__device__ __forceinline__ unsigned f2ord(float f) {
    unsigned b = __float_as_uint(f);
    return (b & 0x80000000u) ? ~b : (b | 0x80000000u);
}
__device__ __forceinline__ ull warp_max_bfly(ull m) {
#pragma unroll
    for (int o = 16; o > 0; o >>= 1) {
        ull other = __shfl_xor_sync(0xffffffffu, m, o);
        if (other > m) m = other;
    }
    return m;
}

__global__ void __launch_bounds__(256) topk_kernel(const int* __restrict__ bid) {
    int i = blockIdx.x;
    int tid = threadIdx.x;
    int lane = tid & 31;
    int wid = tid >> 5;

    __shared__ ull keys[NV];          // 32 KB
    __shared__ ull cmax[NCHUNK];
    __shared__ int chosen[TK + 1 + TKI];
    __shared__ unsigned bitsS[NW];

    int myb = __ldg(&bid[i]);

    const float4* row4 = (const float4*)&g_sim[(size_t)i * NV];
    const int4*   bid4 = (const int4*)bid;
    for (int t = tid; t < NV / 4; t += 256) {
        float4 v = row4[t];
        int4   g = __ldg(&bid4[t]);
        int j0 = t * 4;
        keys[j0 + 0] = ((g.x == myb) ? MSB : 0) | ((ull)f2ord(v.x) << 13) | (unsigned)(NV - (j0 + 0));
        keys[j0 + 1] = ((g.y == myb) ? MSB : 0) | ((ull)f2ord(v.y) << 13) | (unsigned)(NV - (j0 + 1));
        keys[j0 + 2] = ((g.z == myb) ? MSB : 0) | ((ull)f2ord(v.z) << 13) | (unsigned)(NV - (j0 + 2));
        keys[j0 + 3] = ((g.w == myb) ? MSB : 0) | ((ull)f2ord(v.w) << 13) | (unsigned)(NV - (j0 + 3));
    }
    for (int w = tid; w < NW; w += 256) bitsS[w] = 0;
    __syncthreads();

#pragma unroll 1
    for (int phase = 0; phase < 2; phase++) {
        ull xm = phase ? MSB : 0ull;
        int cnt  = phase ? TKI : (TK + 1);
        int base = phase ? (TK + 1) : 0;

#pragma unroll
        for (int cc = 0; cc < 8; cc++) {
            int c = wid * 8 + cc;
            ull a = keys[c * 64 + lane] ^ xm;
            ull b = keys[c * 64 + 32 + lane] ^ xm;
            ull m = a > b ? a : b;
            m = warp_max_bfly(m);
            if (lane == 0) cmax[c] = m;
        }
        __syncthreads();

        if (wid == 0) {
#pragma unroll 1
            for (int t = 0; t < cnt; t++) {
                ull a = cmax[lane];
                ull b = cmax[lane + 32];
                ull m = a > b ? a : b;
                m = warp_max_bfly(m);
                int j = NV - (int)(m & 0x1FFFull);
                int c = j >> 6;
                if (lane == 0) {
                    chosen[base + t] = j;
                    keys[j] = MSB;
                }
                __syncwarp();
                ull ra = keys[c * 64 + lane] ^ xm;
                ull rb = keys[c * 64 + 32 + lane] ^ xm;
                ull rm = ra > rb ? ra : rb;
                rm = warp_max_bfly(rm);
                if (lane == 0) cmax[c] = rm;
                __syncwarp();
            }
        }
        __syncthreads();
    }

    if (tid < NSEL) {
        int j = (tid < TK) ? chosen[1 + tid] : chosen[(TK + 1) + (tid - TK)];
        g_knn[i * NSEL + tid] = j;
        atomicOr(&bitsS[j >> 5], 1u << (j & 31));
    }
    __syncthreads();
    for (int w = tid; w < NW; w += 256) g_bits[i * NW + w] = bitsS[w];
}

// ============================================================================
// Phase 3: mutual check -> scatter locality + all_close
// ============================================================================
__global__ void __launch_bounds__(256) finalize_kernel(
    const float* __restrict__ adj, const int* __restrict__ cl,
    float* __restrict__ out) {
    int id = blockIdx.x * blockDim.x + threadIdx.x;
    if (id >= NV * NSEL) return;
    int i = id / NSEL;
    int j = g_knn[id];

    bool mut = (j != i) && ((g_bits[j * NW + (i >> 5)] >> (i & 31)) & 1u);
    if (mut) out[(size_t)i * NV + j] = adj[(size_t)i * NV + j];

    bool ac = mut;
    if (!ac) {
        ac = true;
#pragma unroll
        for (int m = 0; m < MLAB; m++)
            if (cl[m * NV + i] != cl[m * NV + j]) ac = false;
    }
    out[(size_t)NV * NV + id] = ac ? 1.0f : 0.0f;
}

// ============================================================================
extern "C" void kernel_launch(void* const* d_in, const int* in_sizes, int n_in,
                              void* d_out, int out_size) {
    const float* adj = (const float*)d_in[0];
    const float* E   = (const float*)d_in[1];
    const int*   bid = (const int*)d_in[2];
    const int*   cl  = (const int*)d_in[3];
    float* out = (float*)d_out;

    cudaMemsetAsync(out, 0, (size_t)NV * NV * sizeof(float));
    dim3 grid(NV / 128, NV / 128);
    gemm_sym_kernel<<<grid, 256>>>(E);
    topk_kernel<<<NV, 256>>>(bid);
    finalize_kernel<<<(NV * NSEL + 255) / 256, 256>>>(adj, cl, out);
}